// round 4
// baseline (speedup 1.0000x reference)
#include <cuda_runtime.h>
#include <cstdint>

// Problem constants
static constexpr int  Bc  = 2;
static constexpr int  Tc  = 2048;
static constexpr int  Dc  = 1024;
static constexpr int  Hc  = 16;
static constexpr long long OUT_ELEMS = (long long)Bc * Tc * Dc;          // 4194304
static constexpr long long W_ELEMS   = (long long)Bc * Hc * Tc * Tc;     // 134217728

// Scratch (allocation-free rule: __device__ globals)
__device__ float g_q[Bc * Tc * Dc];
__device__ float g_k[Bc * Tc * Dc];
__device__ float g_v[Bc * Tc * Dc];
__device__ float g_attn[Bc * Tc * Dc];
__device__ float g_weights[(size_t)Bc * Hc * Tc * Tc];  // fallback if out_size lacks weights

// ---------------------------------------------------------------------------
__device__ __forceinline__ uint32_t f2tf(float x) {
    uint32_t r;
    asm("cvt.rna.tf32.f32 %0, %1;" : "=r"(r) : "f"(x));
    return r;
}

__device__ __forceinline__ void mma_tf32(float* c, const uint32_t* a, const uint32_t* b) {
    asm volatile(
        "mma.sync.aligned.m16n8k8.row.col.f32.tf32.tf32.f32 "
        "{%0,%1,%2,%3}, {%4,%5,%6,%7}, {%8,%9}, {%0,%1,%2,%3};\n"
        : "+f"(c[0]), "+f"(c[1]), "+f"(c[2]), "+f"(c[3])
        : "r"(a[0]), "r"(a[1]), "r"(a[2]), "r"(a[3]), "r"(b[0]), "r"(b[1]));
}

// ---------------------------------------------------------------------------
// Projection GEMM-NT: C[4096,1024] = A[4096,1024] @ W[1024,1024]^T
// TF32 converted at smem-store; paired layouts -> LDS.64 fragment loads.
// grid (8, 32, z); z selects one of 3 independent (A,W,C) triples.
// ---------------------------------------------------------------------------
__global__ __launch_bounds__(256, 2) void proj_nt(
    const float* __restrict__ A0, const float* __restrict__ W0, float* __restrict__ C0,
    const float* __restrict__ A1, const float* __restrict__ W1, float* __restrict__ C1,
    const float* __restrict__ A2, const float* __restrict__ W2, float* __restrict__ C2)
{
    // As2: row-pairs (m, m+8): [pr 0..63][k 0..31] uint2, stride 72 words (==8 mod 32)
    // Bs2: k-pairs (k, k+4):   [n 0..127][kc 0..3][tg 0..3] uint2, stride 40 words
    __shared__ uint32_t As2[64 * 72];
    __shared__ uint32_t Bs2[128 * 40];

    const int z = blockIdx.z;
    const float* A = z == 0 ? A0 : (z == 1 ? A1 : A2);
    const float* W = z == 0 ? W0 : (z == 1 ? W1 : W2);
    float*       C = z == 0 ? C0 : (z == 1 ? C1 : C2);

    const float* Ab = A + (long long)blockIdx.y * 128 * 1024;
    const float* Wb = W + (long long)blockIdx.x * 128 * 1024;
    float*       Cb = C + (long long)blockIdx.y * 128 * 1024 + blockIdx.x * 128;

    const int t = threadIdx.x, warp = t >> 5, lane = t & 31;
    const int g = lane >> 2, tg = lane & 3;
    const int m_half = (warp & 1);        // 2 warps along M (64 rows each)
    const int n_base = (warp >> 1) * 32;  // 4 warps along N

    float acc[4][4][4];
#pragma unroll
    for (int i = 0; i < 4; i++)
#pragma unroll
        for (int j = 0; j < 4; j++)
#pragma unroll
            for (int r = 0; r < 4; r++) acc[i][j][r] = 0.f;

    for (int k0 = 0; k0 < 1024; k0 += 32) {
        // A: load rows r and r+8, store pairs
#pragma unroll
        for (int i = 0; i < 2; i++) {
            const int idx = i * 256 + t;
            const int pr = idx >> 3, c4 = (idx & 7) * 4;
            const int r = (pr >> 3) * 16 + (pr & 7);
            const float* s0 = Ab + (long long)r * 1024 + k0 + c4;
            float4 lo = *(const float4*)s0;
            float4 hi = *(const float4*)(s0 + 8 * 1024);
            uint32_t* d = &As2[pr * 72 + c4 * 2];
            ((uint2*)d)[0] = make_uint2(f2tf(lo.x), f2tf(hi.x));
            ((uint2*)d)[1] = make_uint2(f2tf(lo.y), f2tf(hi.y));
            ((uint2*)d)[2] = make_uint2(f2tf(lo.z), f2tf(hi.z));
            ((uint2*)d)[3] = make_uint2(f2tf(lo.w), f2tf(hi.w));
        }
        // B: load cols (k, k+4) pairs
#pragma unroll
        for (int i = 0; i < 2; i++) {
            const int idx = i * 256 + t;
            const int n = idx >> 2, c8 = (idx & 3) * 8;
            const float* s0 = Wb + (long long)n * 1024 + k0 + c8;
            float4 lo = *(const float4*)s0;
            float4 hi = *(const float4*)(s0 + 4);
            uint32_t* d = &Bs2[n * 40 + c8];
            ((uint2*)d)[0] = make_uint2(f2tf(lo.x), f2tf(hi.x));
            ((uint2*)d)[1] = make_uint2(f2tf(lo.y), f2tf(hi.y));
            ((uint2*)d)[2] = make_uint2(f2tf(lo.z), f2tf(hi.z));
            ((uint2*)d)[3] = make_uint2(f2tf(lo.w), f2tf(hi.w));
        }
        __syncthreads();

#pragma unroll
        for (int kc = 0; kc < 4; kc++) {
            uint32_t af[4][4];
#pragma unroll
            for (int mi = 0; mi < 4; mi++) {
                const int rowp = (m_half * 4 + mi) * 8 + g;
                uint2 qa = *(const uint2*)&As2[rowp * 72 + (kc * 8 + tg) * 2];
                uint2 qb = *(const uint2*)&As2[rowp * 72 + (kc * 8 + 4 + tg) * 2];
                af[mi][0] = qa.x; af[mi][1] = qa.y; af[mi][2] = qb.x; af[mi][3] = qb.y;
            }
#pragma unroll
            for (int ni = 0; ni < 4; ni++) {
                uint2 bb = *(const uint2*)&Bs2[(n_base + ni * 8 + g) * 40 + kc * 8 + tg * 2];
#pragma unroll
                for (int mi = 0; mi < 4; mi++)
                    mma_tf32(acc[mi][ni], af[mi], &bb.x);
            }
        }
        __syncthreads();
    }

#pragma unroll
    for (int mi = 0; mi < 4; mi++) {
#pragma unroll
        for (int ni = 0; ni < 4; ni++) {
            const int row = m_half * 64 + mi * 16 + g;
            const int col = n_base + ni * 8 + tg * 2;
            *(float2*)(Cb + (long long)row * 1024 + col) =
                make_float2(acc[mi][ni][0], acc[mi][ni][1]);
            *(float2*)(Cb + (long long)(row + 8) * 1024 + col) =
                make_float2(acc[mi][ni][2], acc[mi][ni][3]);
        }
    }
}

// ---------------------------------------------------------------------------
// Fused attention: per CTA = 128 query rows of one (b,h).
// Pass 1: stream K tiles, running row max m / sum l (online softmax stats).
// Pass 2: recompute S tile, p = exp(s-m)/l, write weights, O += P@V.
// smem word offsets (uint32 units):
//   Qs  [128][68]          0      (tf32, simple layout; A-frags hoisted once)
//   Ks2 [128 n][72]        8704   (k-pairs (k,k+4) as uint2, stride 72)
//   Vs2 [64 row][136]      17920  (row = kc*4+tg holds (V[k], V[k+4]) uint2)
//   Ps2 [8 warp][8 g][264] 26624  (row-pairs (g, g+8) as uint2)
// total 43520 words = 174080 B
// ---------------------------------------------------------------------------
static constexpr int FA_SMEM_BYTES = 174080;

__global__ __launch_bounds__(256) void fused_attn(
    const float* __restrict__ q, const float* __restrict__ k, const float* __restrict__ v,
    float* __restrict__ wts, float* __restrict__ attn)
{
    extern __shared__ uint32_t sm[];
    uint32_t* Qs  = sm;
    uint32_t* Ks2 = sm + 8704;
    uint32_t* Vs2 = sm + 17920;
    uint32_t* Ps2 = sm + 26624;

    const int bh = blockIdx.z;
    const int b = bh >> 4, h = bh & 15;
    const int qbase = blockIdx.y * 128;
    const int t = threadIdx.x, warp = t >> 5, lane = t & 31;
    const int g = lane >> 2, tg = lane & 3;
    const int wm = warp * 16;  // warp's query-row base within tile

    const float* qp = q + ((long long)(b * Tc + qbase)) * Dc + h * 64;
    const float* kp = k + ((long long)b * Tc) * Dc + h * 64;
    const float* vp = v + ((long long)b * Tc) * Dc + h * 64;

    // ---- load Q tile (tf32) ----
#pragma unroll
    for (int i = 0; i < 8; i++) {
        const int idx = i * 256 + t;
        const int r = idx >> 4, c = (idx & 15) * 4;
        float4 x = *(const float4*)(qp + (long long)r * Dc + c);
        uint32_t* d = &Qs[r * 68 + c];
        d[0] = f2tf(x.x); d[1] = f2tf(x.y); d[2] = f2tf(x.z); d[3] = f2tf(x.w);
    }
    __syncthreads();

    // hoist Q A-fragments (constant for the whole kernel)
    uint32_t af[8][4];
#pragma unroll
    for (int kc = 0; kc < 8; kc++) {
        af[kc][0] = Qs[(wm + g) * 68 + kc * 8 + tg];
        af[kc][1] = Qs[(wm + 8 + g) * 68 + kc * 8 + tg];
        af[kc][2] = Qs[(wm + g) * 68 + kc * 8 + 4 + tg];
        af[kc][3] = Qs[(wm + 8 + g) * 68 + kc * 8 + 4 + tg];
    }

    float m0 = -1e30f, m1 = -1e30f, l0 = 0.f, l1 = 0.f;

    // ================= PASS 1: row max / sum =================
    for (int j = 0; j < 16; j++) {
        // load K tile (k-pairs)
#pragma unroll
        for (int i = 0; i < 4; i++) {
            const int idx = i * 256 + t;
            const int r = idx >> 3, c8 = (idx & 7) * 8;
            const float* s0 = kp + (long long)(j * 128 + r) * Dc + c8;
            float4 lo = *(const float4*)s0;
            float4 hi = *(const float4*)(s0 + 4);
            uint32_t* d = &Ks2[r * 72 + c8];
            ((uint2*)d)[0] = make_uint2(f2tf(lo.x), f2tf(hi.x));
            ((uint2*)d)[1] = make_uint2(f2tf(lo.y), f2tf(hi.y));
            ((uint2*)d)[2] = make_uint2(f2tf(lo.z), f2tf(hi.z));
            ((uint2*)d)[3] = make_uint2(f2tf(lo.w), f2tf(hi.w));
        }
        __syncthreads();

        float sacc[16][4];
#pragma unroll
        for (int nf = 0; nf < 16; nf++) {
            sacc[nf][0] = sacc[nf][1] = sacc[nf][2] = sacc[nf][3] = 0.f;
            const int base = (nf * 8 + g) * 72;
#pragma unroll
            for (int kc = 0; kc < 8; kc++) {
                uint2 bb = *(const uint2*)&Ks2[base + kc * 8 + tg * 2];
                mma_tf32(sacc[nf], af[kc], &bb.x);
            }
        }

        float tm0 = -1e30f, tm1 = -1e30f;
#pragma unroll
        for (int nf = 0; nf < 16; nf++) {
#pragma unroll
            for (int r = 0; r < 4; r++) sacc[nf][r] *= 0.125f;
            tm0 = fmaxf(tm0, fmaxf(sacc[nf][0], sacc[nf][1]));
            tm1 = fmaxf(tm1, fmaxf(sacc[nf][2], sacc[nf][3]));
        }
        tm0 = fmaxf(tm0, __shfl_xor_sync(0xffffffffu, tm0, 1));
        tm0 = fmaxf(tm0, __shfl_xor_sync(0xffffffffu, tm0, 2));
        tm1 = fmaxf(tm1, __shfl_xor_sync(0xffffffffu, tm1, 1));
        tm1 = fmaxf(tm1, __shfl_xor_sync(0xffffffffu, tm1, 2));

        const float mn0 = fmaxf(m0, tm0), mn1 = fmaxf(m1, tm1);
        float ts0 = 0.f, ts1 = 0.f;
#pragma unroll
        for (int nf = 0; nf < 16; nf++) {
            ts0 += __expf(sacc[nf][0] - mn0) + __expf(sacc[nf][1] - mn0);
            ts1 += __expf(sacc[nf][2] - mn1) + __expf(sacc[nf][3] - mn1);
        }
        ts0 += __shfl_xor_sync(0xffffffffu, ts0, 1);
        ts0 += __shfl_xor_sync(0xffffffffu, ts0, 2);
        ts1 += __shfl_xor_sync(0xffffffffu, ts1, 1);
        ts1 += __shfl_xor_sync(0xffffffffu, ts1, 2);

        l0 = l0 * __expf(m0 - mn0) + ts0;  m0 = mn0;
        l1 = l1 * __expf(m1 - mn1) + ts1;  m1 = mn1;
        __syncthreads();
    }

    const float inv0 = 1.0f / l0;
    const float inv1 = 1.0f / l1;

    // ================= PASS 2: weights + PV =================
    float oacc[8][4];
#pragma unroll
    for (int nf = 0; nf < 8; nf++)
#pragma unroll
        for (int r = 0; r < 4; r++) oacc[nf][r] = 0.f;

    uint32_t* Pw = &Ps2[warp * 8 * 264];

    for (int j = 0; j < 16; j++) {
        // load K tile
#pragma unroll
        for (int i = 0; i < 4; i++) {
            const int idx = i * 256 + t;
            const int r = idx >> 3, c8 = (idx & 7) * 8;
            const float* s0 = kp + (long long)(j * 128 + r) * Dc + c8;
            float4 lo = *(const float4*)s0;
            float4 hi = *(const float4*)(s0 + 4);
            uint32_t* d = &Ks2[r * 72 + c8];
            ((uint2*)d)[0] = make_uint2(f2tf(lo.x), f2tf(hi.x));
            ((uint2*)d)[1] = make_uint2(f2tf(lo.y), f2tf(hi.y));
            ((uint2*)d)[2] = make_uint2(f2tf(lo.z), f2tf(hi.z));
            ((uint2*)d)[3] = make_uint2(f2tf(lo.w), f2tf(hi.w));
        }
        // load V tile (row-pairs (k, k+4))
#pragma unroll
        for (int i = 0; i < 4; i++) {
            const int idx = i * 256 + t;
            const int p = idx >> 4;             // 0..63
            const int c4 = (idx & 15) * 4;
            const int klo = (p >> 2) * 8 + (p & 3);
            const float* s0 = vp + (long long)(j * 128 + klo) * Dc + c4;
            float4 lo = *(const float4*)s0;
            float4 hi = *(const float4*)(s0 + 4 * Dc);
            uint32_t* d = &Vs2[p * 136 + c4 * 2];
            ((uint2*)d)[0] = make_uint2(f2tf(lo.x), f2tf(hi.x));
            ((uint2*)d)[1] = make_uint2(f2tf(lo.y), f2tf(hi.y));
            ((uint2*)d)[2] = make_uint2(f2tf(lo.z), f2tf(hi.z));
            ((uint2*)d)[3] = make_uint2(f2tf(lo.w), f2tf(hi.w));
        }
        __syncthreads();

        // recompute S tile
        float sacc[16][4];
#pragma unroll
        for (int nf = 0; nf < 16; nf++) {
            sacc[nf][0] = sacc[nf][1] = sacc[nf][2] = sacc[nf][3] = 0.f;
            const int base = (nf * 8 + g) * 72;
#pragma unroll
            for (int kc = 0; kc < 8; kc++) {
                uint2 bb = *(const uint2*)&Ks2[base + kc * 8 + tg * 2];
                mma_tf32(sacc[nf], af[kc], &bb.x);
            }
        }

        // normalize, write weights, stash tf32 P
        float* wrow0 = wts + ((long long)bh * Tc + qbase + wm + g) * Tc + j * 128;
        float* wrow1 = wrow0 + 8 * Tc;
#pragma unroll
        for (int nf = 0; nf < 16; nf++) {
            const int c = nf * 8 + tg * 2;
            const float p00 = __expf(sacc[nf][0] * 0.125f - m0) * inv0;
            const float p01 = __expf(sacc[nf][1] * 0.125f - m0) * inv0;
            const float p10 = __expf(sacc[nf][2] * 0.125f - m1) * inv1;
            const float p11 = __expf(sacc[nf][3] * 0.125f - m1) * inv1;
            *(float2*)(wrow0 + c) = make_float2(p00, p01);
            *(float2*)(wrow1 + c) = make_float2(p10, p11);
            *(uint2*)&Pw[g * 264 + c * 2]       = make_uint2(f2tf(p00), f2tf(p10));
            *(uint2*)&Pw[g * 264 + (c + 1) * 2] = make_uint2(f2tf(p01), f2tf(p11));
        }
        __syncwarp();

        // O += P @ V
#pragma unroll
        for (int kc = 0; kc < 16; kc++) {
            uint2 qa = *(const uint2*)&Pw[g * 264 + (kc * 8 + tg) * 2];
            uint2 qb = *(const uint2*)&Pw[g * 264 + (kc * 8 + 4 + tg) * 2];
            uint32_t pa[4] = {qa.x, qa.y, qb.x, qb.y};
#pragma unroll
            for (int nf = 0; nf < 8; nf++) {
                uint2 bb = *(const uint2*)&Vs2[(kc * 4 + tg) * 136 + (nf * 8 + g) * 2];
                mma_tf32(oacc[nf], pa, &bb.x);
            }
        }
        __syncthreads();
    }

    // write O (goes to attn buffer [B,T,D] interleaved by head)
    float* op0 = attn + ((long long)(b * Tc + qbase + wm + g)) * Dc + h * 64;
    float* op1 = op0 + 8 * Dc;
#pragma unroll
    for (int nf = 0; nf < 8; nf++) {
        const int c = nf * 8 + tg * 2;
        *(float2*)(op0 + c) = make_float2(oacc[nf][0], oacc[nf][1]);
        *(float2*)(op1 + c) = make_float2(oacc[nf][2], oacc[nf][3]);
    }
}

// ---------------------------------------------------------------------------
extern "C" void kernel_launch(void* const* d_in, const int* /*in_sizes*/, int /*n_in*/,
                              void* d_out, int out_size)
{
    const float* query = (const float*)d_in[0];
    const float* key_i = (const float*)d_in[1];
    const float* value = (const float*)d_in[2];
    const float* Wq    = (const float*)d_in[3];
    const float* Wk    = (const float*)d_in[4];
    const float* Wv    = (const float*)d_in[5];
    const float* Wo    = (const float*)d_in[6];
    float* out = (float*)d_out;

    float *q, *k, *v, *attn, *wbuf;
    cudaGetSymbolAddress((void**)&q,    g_q);
    cudaGetSymbolAddress((void**)&k,    g_k);
    cudaGetSymbolAddress((void**)&v,    g_v);
    cudaGetSymbolAddress((void**)&attn, g_attn);
    if ((long long)out_size >= OUT_ELEMS + W_ELEMS) {
        wbuf = out + OUT_ELEMS;                 // tuple-concat output: [out | weights]
    } else {
        cudaGetSymbolAddress((void**)&wbuf, g_weights);
    }

    cudaFuncSetAttribute(fused_attn, cudaFuncAttributeMaxDynamicSharedMemorySize,
                         FA_SMEM_BYTES);

    // 1) Q/K/V projections in one launch (z selects operand triple)
    proj_nt<<<dim3(8, 32, 3), 256>>>(query, Wq, q, key_i, Wk, k, value, Wv, v);

    // 2) fused scores + softmax (weights out) + PV
    fused_attn<<<dim3(1, 16, 32), 256, FA_SMEM_BYTES>>>(q, k, v, wbuf, attn);

    // 3) out = attn @ Wo^T
    proj_nt<<<dim3(8, 32, 1), 256>>>(attn, Wo, out, attn, Wo, out, attn, Wo, out);
}

// round 5
// speedup vs baseline: 1.3504x; 1.3504x over previous
#include <cuda_runtime.h>
#include <cstdint>

// Problem constants
static constexpr int  Bc  = 2;
static constexpr int  Tc  = 2048;
static constexpr int  Dc  = 1024;
static constexpr int  Hc  = 16;
static constexpr long long OUT_ELEMS = (long long)Bc * Tc * Dc;          // 4194304
static constexpr long long W_ELEMS   = (long long)Bc * Hc * Tc * Tc;     // 134217728

// Scratch (allocation-free rule: __device__ globals)
__device__ float g_q[Bc * Tc * Dc];
__device__ float g_k[Bc * Tc * Dc];
__device__ float g_v[Bc * Tc * Dc];
__device__ float g_attn[Bc * Tc * Dc];
__device__ float g_stats[(size_t)Bc * Hc * Tc * 16 * 2];                 // (m,l) per row per col-tile
__device__ float g_weights[(size_t)Bc * Hc * Tc * Tc];  // fallback if out_size lacks weights

// ---------------------------------------------------------------------------
__device__ __forceinline__ uint32_t f2tf(float x) {
    uint32_t r;
    asm("cvt.rna.tf32.f32 %0, %1;" : "=r"(r) : "f"(x));
    return r;
}

__device__ __forceinline__ void mma_tf32(float* c, const uint32_t* a, const uint32_t* b) {
    asm volatile(
        "mma.sync.aligned.m16n8k8.row.col.f32.tf32.tf32.f32 "
        "{%0,%1,%2,%3}, {%4,%5,%6,%7}, {%8,%9}, {%0,%1,%2,%3};\n"
        : "+f"(c[0]), "+f"(c[1]), "+f"(c[2]), "+f"(c[3])
        : "r"(a[0]), "r"(a[1]), "r"(a[2]), "r"(a[3]), "r"(b[0]), "r"(b[1]));
}

// ---------------------------------------------------------------------------
// Projection GEMM-NT: C[4096,1024] = A[4096,1024] @ W[1024,1024]^T
// grid (8, 32, z); z selects one of 3 independent (A,W,C) triples.
// ---------------------------------------------------------------------------
__global__ __launch_bounds__(256, 2) void proj_nt(
    const float* __restrict__ A0, const float* __restrict__ W0, float* __restrict__ C0,
    const float* __restrict__ A1, const float* __restrict__ W1, float* __restrict__ C1,
    const float* __restrict__ A2, const float* __restrict__ W2, float* __restrict__ C2)
{
    __shared__ uint32_t As2[64 * 72];
    __shared__ uint32_t Bs2[128 * 40];

    const int z = blockIdx.z;
    const float* A = z == 0 ? A0 : (z == 1 ? A1 : A2);
    const float* W = z == 0 ? W0 : (z == 1 ? W1 : W2);
    float*       C = z == 0 ? C0 : (z == 1 ? C1 : C2);

    const float* Ab = A + (long long)blockIdx.y * 128 * 1024;
    const float* Wb = W + (long long)blockIdx.x * 128 * 1024;
    float*       Cb = C + (long long)blockIdx.y * 128 * 1024 + blockIdx.x * 128;

    const int t = threadIdx.x, warp = t >> 5, lane = t & 31;
    const int g = lane >> 2, tg = lane & 3;
    const int m_half = (warp & 1);
    const int n_base = (warp >> 1) * 32;

    float acc[4][4][4];
#pragma unroll
    for (int i = 0; i < 4; i++)
#pragma unroll
        for (int j = 0; j < 4; j++)
#pragma unroll
            for (int r = 0; r < 4; r++) acc[i][j][r] = 0.f;

    for (int k0 = 0; k0 < 1024; k0 += 32) {
#pragma unroll
        for (int i = 0; i < 2; i++) {
            const int idx = i * 256 + t;
            const int pr = idx >> 3, c4 = (idx & 7) * 4;
            const int r = (pr >> 3) * 16 + (pr & 7);
            const float* s0 = Ab + (long long)r * 1024 + k0 + c4;
            float4 lo = *(const float4*)s0;
            float4 hi = *(const float4*)(s0 + 8 * 1024);
            uint32_t* d = &As2[pr * 72 + c4 * 2];
            ((uint2*)d)[0] = make_uint2(f2tf(lo.x), f2tf(hi.x));
            ((uint2*)d)[1] = make_uint2(f2tf(lo.y), f2tf(hi.y));
            ((uint2*)d)[2] = make_uint2(f2tf(lo.z), f2tf(hi.z));
            ((uint2*)d)[3] = make_uint2(f2tf(lo.w), f2tf(hi.w));
        }
#pragma unroll
        for (int i = 0; i < 2; i++) {
            const int idx = i * 256 + t;
            const int n = idx >> 2, c8 = (idx & 3) * 8;
            const float* s0 = Wb + (long long)n * 1024 + k0 + c8;
            float4 lo = *(const float4*)s0;
            float4 hi = *(const float4*)(s0 + 4);
            uint32_t* d = &Bs2[n * 40 + c8];
            ((uint2*)d)[0] = make_uint2(f2tf(lo.x), f2tf(hi.x));
            ((uint2*)d)[1] = make_uint2(f2tf(lo.y), f2tf(hi.y));
            ((uint2*)d)[2] = make_uint2(f2tf(lo.z), f2tf(hi.z));
            ((uint2*)d)[3] = make_uint2(f2tf(lo.w), f2tf(hi.w));
        }
        __syncthreads();

#pragma unroll
        for (int kc = 0; kc < 4; kc++) {
            uint32_t af[4][4];
#pragma unroll
            for (int mi = 0; mi < 4; mi++) {
                const int rowp = (m_half * 4 + mi) * 8 + g;
                uint2 qa = *(const uint2*)&As2[rowp * 72 + (kc * 8 + tg) * 2];
                uint2 qb = *(const uint2*)&As2[rowp * 72 + (kc * 8 + 4 + tg) * 2];
                af[mi][0] = qa.x; af[mi][1] = qa.y; af[mi][2] = qb.x; af[mi][3] = qb.y;
            }
#pragma unroll
            for (int ni = 0; ni < 4; ni++) {
                uint2 bb = *(const uint2*)&Bs2[(n_base + ni * 8 + g) * 40 + kc * 8 + tg * 2];
#pragma unroll
                for (int mi = 0; mi < 4; mi++)
                    mma_tf32(acc[mi][ni], af[mi], &bb.x);
            }
        }
        __syncthreads();
    }

#pragma unroll
    for (int mi = 0; mi < 4; mi++) {
#pragma unroll
        for (int ni = 0; ni < 4; ni++) {
            const int row = m_half * 64 + mi * 16 + g;
            const int col = n_base + ni * 8 + tg * 2;
            *(float2*)(Cb + (long long)row * 1024 + col) =
                make_float2(acc[mi][ni][0], acc[mi][ni][1]);
            *(float2*)(Cb + (long long)(row + 8) * 1024 + col) =
                make_float2(acc[mi][ni][2], acc[mi][ni][3]);
        }
    }
}

// ---------------------------------------------------------------------------
// Scores: one CTA = 128x128 tile of S = (Q K^T)/8 for one (b,h).
// K=64 -> load Q/K tiles once, 8 MMA k-chunks. Epilogue computes per-tile
// row (max, sumexp) stats (written to g_stats) and stores raw scaled S.
// smem (words): Qs[128*68] @0, Ks[128*68] @8704, wred[128*4] @17408,
//               mrow[128] @17920, wsum[128*4] @18048  -> 18560 w = 74240 B
// ---------------------------------------------------------------------------
static constexpr int SC_SMEM_BYTES = 18560 * 4;

__global__ __launch_bounds__(256) void scores_kernel(
    const float* __restrict__ q, const float* __restrict__ k,
    float* __restrict__ sraw, float* __restrict__ stats)
{
    extern __shared__ uint32_t sm[];
    uint32_t* Qs  = sm;
    uint32_t* Ks  = sm + 8704;
    float*    wred = (float*)(sm + 17408);   // [128][4]
    float*    mrow = (float*)(sm + 17920);   // [128]
    float*    wsum = (float*)(sm + 18048);   // [128][4]

    const int bh = blockIdx.z;
    const int b = bh >> 4, h = bh & 15;
    const int qbase = blockIdx.y * 128;
    const int nbase = blockIdx.x * 128;
    const int t = threadIdx.x, warp = t >> 5, lane = t & 31;
    const int g = lane >> 2, tg = lane & 3;
    const int m_half = warp & 1;
    const int n_off  = (warp >> 1) * 32;
    const int nwarp  = warp >> 1;

    const float* qp = q + ((long long)(b * Tc + qbase)) * Dc + h * 64;
    const float* kp = k + ((long long)(b * Tc + nbase)) * Dc + h * 64;

    // load tiles (tf32), stride 68 -> conflict-free fragment reads
#pragma unroll
    for (int i = 0; i < 8; i++) {
        const int idx = i * 256 + t;
        const int r = idx >> 4, c4 = (idx & 15) * 4;
        float4 xq = *(const float4*)(qp + (long long)r * Dc + c4);
        float4 xk = *(const float4*)(kp + (long long)r * Dc + c4);
        uint32_t* dq = &Qs[r * 68 + c4];
        dq[0] = f2tf(xq.x); dq[1] = f2tf(xq.y); dq[2] = f2tf(xq.z); dq[3] = f2tf(xq.w);
        uint32_t* dk = &Ks[r * 68 + c4];
        dk[0] = f2tf(xk.x); dk[1] = f2tf(xk.y); dk[2] = f2tf(xk.z); dk[3] = f2tf(xk.w);
    }
    __syncthreads();

    float sacc[4][4][4];
#pragma unroll
    for (int i = 0; i < 4; i++)
#pragma unroll
        for (int j = 0; j < 4; j++)
#pragma unroll
            for (int r = 0; r < 4; r++) sacc[i][j][r] = 0.f;

#pragma unroll
    for (int kc = 0; kc < 8; kc++) {
        uint32_t af[4][4], bf[4][2];
#pragma unroll
        for (int mi = 0; mi < 4; mi++) {
            const int r0 = (m_half * 64 + mi * 16 + g) * 68;
            af[mi][0] = Qs[r0 + kc * 8 + tg];
            af[mi][1] = Qs[r0 + 8 * 68 + kc * 8 + tg];
            af[mi][2] = Qs[r0 + kc * 8 + 4 + tg];
            af[mi][3] = Qs[r0 + 8 * 68 + kc * 8 + 4 + tg];
        }
#pragma unroll
        for (int ni = 0; ni < 4; ni++) {
            const int n0 = (n_off + ni * 8 + g) * 68;
            bf[ni][0] = Ks[n0 + kc * 8 + tg];
            bf[ni][1] = Ks[n0 + kc * 8 + 4 + tg];
        }
#pragma unroll
        for (int mi = 0; mi < 4; mi++)
#pragma unroll
            for (int ni = 0; ni < 4; ni++)
                mma_tf32(sacc[mi][ni], af[mi], bf[ni]);
    }

    // scale
#pragma unroll
    for (int mi = 0; mi < 4; mi++)
#pragma unroll
        for (int ni = 0; ni < 4; ni++)
#pragma unroll
            for (int r = 0; r < 4; r++) sacc[mi][ni][r] *= 0.125f;

    // ---- per-tile row max ----
#pragma unroll
    for (int mi = 0; mi < 4; mi++) {
        float v0 = -1e30f, v1 = -1e30f;
#pragma unroll
        for (int ni = 0; ni < 4; ni++) {
            v0 = fmaxf(v0, fmaxf(sacc[mi][ni][0], sacc[mi][ni][1]));
            v1 = fmaxf(v1, fmaxf(sacc[mi][ni][2], sacc[mi][ni][3]));
        }
        v0 = fmaxf(v0, __shfl_xor_sync(0xffffffffu, v0, 1));
        v0 = fmaxf(v0, __shfl_xor_sync(0xffffffffu, v0, 2));
        v1 = fmaxf(v1, __shfl_xor_sync(0xffffffffu, v1, 1));
        v1 = fmaxf(v1, __shfl_xor_sync(0xffffffffu, v1, 2));
        if (tg == 0) {
            wred[(m_half * 64 + mi * 16 + g) * 4 + nwarp]     = v0;
            wred[(m_half * 64 + mi * 16 + 8 + g) * 4 + nwarp] = v1;
        }
    }
    __syncthreads();
    if (t < 128) {
        float m = fmaxf(fmaxf(wred[t * 4], wred[t * 4 + 1]),
                        fmaxf(wred[t * 4 + 2], wred[t * 4 + 3]));
        mrow[t] = m;
    }
    __syncthreads();

    // ---- per-tile row sumexp ----
#pragma unroll
    for (int mi = 0; mi < 4; mi++) {
        const float m0 = mrow[m_half * 64 + mi * 16 + g];
        const float m1 = mrow[m_half * 64 + mi * 16 + 8 + g];
        float s0 = 0.f, s1 = 0.f;
#pragma unroll
        for (int ni = 0; ni < 4; ni++) {
            s0 += __expf(sacc[mi][ni][0] - m0) + __expf(sacc[mi][ni][1] - m0);
            s1 += __expf(sacc[mi][ni][2] - m1) + __expf(sacc[mi][ni][3] - m1);
        }
        s0 += __shfl_xor_sync(0xffffffffu, s0, 1);
        s0 += __shfl_xor_sync(0xffffffffu, s0, 2);
        s1 += __shfl_xor_sync(0xffffffffu, s1, 1);
        s1 += __shfl_xor_sync(0xffffffffu, s1, 2);
        if (tg == 0) {
            wsum[(m_half * 64 + mi * 16 + g) * 4 + nwarp]     = s0;
            wsum[(m_half * 64 + mi * 16 + 8 + g) * 4 + nwarp] = s1;
        }
    }
    __syncthreads();
    if (t < 128) {
        float l = wsum[t * 4] + wsum[t * 4 + 1] + wsum[t * 4 + 2] + wsum[t * 4 + 3];
        float2* st = (float2*)(stats + (((long long)bh * Tc + qbase + t) * 16 + blockIdx.x) * 2);
        *st = make_float2(mrow[t], l);
    }

    // ---- store raw scaled S ----
#pragma unroll
    for (int mi = 0; mi < 4; mi++) {
#pragma unroll
        for (int ni = 0; ni < 4; ni++) {
            const int row = m_half * 64 + mi * 16 + g;
            const int col = nbase + n_off + ni * 8 + tg * 2;
            float* w0 = sraw + ((long long)bh * Tc + qbase + row) * Tc + col;
            *(float2*)w0 = make_float2(sacc[mi][ni][0], sacc[mi][ni][1]);
            *(float2*)(w0 + 8 * Tc) = make_float2(sacc[mi][ni][2], sacc[mi][ni][3]);
        }
    }
}

// ---------------------------------------------------------------------------
// softmax+PV: one CTA = 128 query rows of one (b,h).
// Reduce 16 per-tile stats -> (m, 1/l) per row; then stream S (in place ->
// normalized W), stash tf32 P in smem, accumulate O = P @ V with MMA.
// smem (words): Pp[128*68] @0, Vs[64*72] @8704, rstat float2[128] @13312
//   -> 13568 w = 54272 B
// ---------------------------------------------------------------------------
static constexpr int SPV_SMEM_BYTES = 13568 * 4;

__global__ __launch_bounds__(256) void softmax_pv(
    const float* __restrict__ v, float* __restrict__ w,
    const float* __restrict__ stats, float* __restrict__ attn)
{
    extern __shared__ uint32_t sm[];
    uint32_t* Pp = sm;
    uint32_t* Vs = sm + 8704;
    float2*   rstat = (float2*)(sm + 13312);

    const int bh = blockIdx.z;
    const int b = bh >> 4, h = bh & 15;
    const int qbase = blockIdx.y * 128;
    const int t = threadIdx.x, warp = t >> 5, lane = t & 31;
    const int g = lane >> 2, tg = lane & 3;

    const float* vp = v + ((long long)b * Tc) * Dc + h * 64;
    float* wb = w + ((long long)bh * Tc + qbase) * Tc;

    // reduce per-tile stats -> final (m, 1/l)
    if (t < 128) {
        const float2* st = (const float2*)(stats + (((long long)bh * Tc + qbase + t) * 16) * 2);
        float m = -1e30f;
        float2 sl[16];
#pragma unroll
        for (int j = 0; j < 16; j++) { sl[j] = st[j]; m = fmaxf(m, sl[j].x); }
        float l = 0.f;
#pragma unroll
        for (int j = 0; j < 16; j++) l += sl[j].y * __expf(sl[j].x - m);
        rstat[t] = make_float2(m, 1.0f / l);
    }
    __syncthreads();

    float oacc[8][4];
#pragma unroll
    for (int nf = 0; nf < 8; nf++)
#pragma unroll
        for (int r = 0; r < 4; r++) oacc[nf][r] = 0.f;

    for (int sub = 0; sub < 32; sub++) {
        // V subtile (64 seq rows x 64 dk), stride 72
#pragma unroll
        for (int i = 0; i < 4; i++) {
            const int idx = i * 256 + t;
            const int kk = idx >> 4, c4 = (idx & 15) * 4;
            float4 x = *(const float4*)(vp + (long long)(sub * 64 + kk) * Dc + c4);
            uint32_t* d = &Vs[kk * 72 + c4];
            d[0] = f2tf(x.x); d[1] = f2tf(x.y); d[2] = f2tf(x.z); d[3] = f2tf(x.w);
        }
        // stream S -> normalized W (in place) + tf32 P to smem (stride 68)
#pragma unroll
        for (int i = 0; i < 8; i++) {
            const int idx = i * 256 + t;
            const int row = idx >> 4, c4 = (idx & 15) * 4;
            float* gp = wb + (long long)row * Tc + sub * 64 + c4;
            float4 s = *(const float4*)gp;
            const float2 ms = rstat[row];
            float4 p;
            p.x = __expf(s.x - ms.x) * ms.y;
            p.y = __expf(s.y - ms.x) * ms.y;
            p.z = __expf(s.z - ms.x) * ms.y;
            p.w = __expf(s.w - ms.x) * ms.y;
            *(float4*)gp = p;
            uint32_t* d = &Pp[row * 68 + c4];
            d[0] = f2tf(p.x); d[1] = f2tf(p.y); d[2] = f2tf(p.z); d[3] = f2tf(p.w);
        }
        __syncthreads();

        // O += P @ V
#pragma unroll
        for (int kc = 0; kc < 8; kc++) {
            const int r0 = (warp * 16 + g) * 68;
            uint32_t a[4];
            a[0] = Pp[r0 + kc * 8 + tg];
            a[1] = Pp[r0 + 8 * 68 + kc * 8 + tg];
            a[2] = Pp[r0 + kc * 8 + 4 + tg];
            a[3] = Pp[r0 + 8 * 68 + kc * 8 + 4 + tg];
#pragma unroll
            for (int nf = 0; nf < 8; nf++) {
                uint32_t bfr[2];
                bfr[0] = Vs[(kc * 8 + tg) * 72 + nf * 8 + g];
                bfr[1] = Vs[(kc * 8 + 4 + tg) * 72 + nf * 8 + g];
                mma_tf32(oacc[nf], a, bfr);
            }
        }
        __syncthreads();
    }

    // write O into attn buffer [B,T,D]
    float* op0 = attn + ((long long)(b * Tc + qbase + warp * 16 + g)) * Dc + h * 64;
    float* op1 = op0 + 8 * Dc;
#pragma unroll
    for (int nf = 0; nf < 8; nf++) {
        const int c = nf * 8 + tg * 2;
        *(float2*)(op0 + c) = make_float2(oacc[nf][0], oacc[nf][1]);
        *(float2*)(op1 + c) = make_float2(oacc[nf][2], oacc[nf][3]);
    }
}

// ---------------------------------------------------------------------------
extern "C" void kernel_launch(void* const* d_in, const int* /*in_sizes*/, int /*n_in*/,
                              void* d_out, int out_size)
{
    const float* query = (const float*)d_in[0];
    const float* key_i = (const float*)d_in[1];
    const float* value = (const float*)d_in[2];
    const float* Wq    = (const float*)d_in[3];
    const float* Wk    = (const float*)d_in[4];
    const float* Wv    = (const float*)d_in[5];
    const float* Wo    = (const float*)d_in[6];
    float* out = (float*)d_out;

    float *q, *k, *v, *attn, *stats, *wbuf;
    cudaGetSymbolAddress((void**)&q,     g_q);
    cudaGetSymbolAddress((void**)&k,     g_k);
    cudaGetSymbolAddress((void**)&v,     g_v);
    cudaGetSymbolAddress((void**)&attn,  g_attn);
    cudaGetSymbolAddress((void**)&stats, g_stats);
    if ((long long)out_size >= OUT_ELEMS + W_ELEMS) {
        wbuf = out + OUT_ELEMS;                 // tuple-concat output: [out | weights]
    } else {
        cudaGetSymbolAddress((void**)&wbuf, g_weights);
    }

    cudaFuncSetAttribute(scores_kernel, cudaFuncAttributeMaxDynamicSharedMemorySize,
                         SC_SMEM_BYTES);
    cudaFuncSetAttribute(softmax_pv, cudaFuncAttributeMaxDynamicSharedMemorySize,
                         SPV_SMEM_BYTES);

    // 1) Q/K/V projections in one launch
    proj_nt<<<dim3(8, 32, 3), 256>>>(query, Wq, q, key_i, Wk, k, value, Wv, v);

    // 2) raw scores + per-tile softmax stats
    scores_kernel<<<dim3(16, 16, 32), 256, SC_SMEM_BYTES>>>(q, k, wbuf, stats);

    // 3) normalize (write weights in place) + PV
    softmax_pv<<<dim3(1, 16, 32), 256, SPV_SMEM_BYTES>>>(v, wbuf, stats, attn);

    // 4) out = attn @ Wo^T
    proj_nt<<<dim3(8, 32, 1), 256>>>(attn, Wo, out, attn, Wo, out, attn, Wo, out);
}